// round 5
// baseline (speedup 1.0000x reference)
#include <cuda_runtime.h>
#include <cstdint>

// Problem constants
#define Bn  4
#define Sn  2048
#define Dn  1024
#define Hn  16
#define DKn 64
#define Mn  (Bn * Sn)   // 8192

// Scratch (allocation-free: __device__ globals)
__device__ float g_Q[(size_t)Bn * Hn * Sn * DKn];     // [B,H,S,DK]
__device__ float g_K[(size_t)Bn * Hn * Sn * DKn];     // [B,H,S,DK]
__device__ float g_V[(size_t)Bn * Hn * Sn * DKn];     // [B,H,S,DK]
__device__ float g_attn[(size_t)Bn * Sn * Dn];        // [B,S,D]

// ---------------------------------------------------------------------------
// Fast exp on the FMA pipe (avoids MUFU.EX2 throughput wall: 268M exps).
// Valid for x <= 0 (softmax arguments). Rel err ~1e-7.
// ---------------------------------------------------------------------------
__device__ __forceinline__ float fast_exp(float x) {
    float t = x * 1.44269504088896341f;          // x * log2(e)
    t = fmaxf(t, -126.0f);                       // clamp (masked -1e9 path)
    float z = t + 12582912.0f;                   // round-to-nearest-int trick
    int   e = __float_as_int(z) - 0x4B400000;    // integer part
    float fi = z - 12582912.0f;
    float f = t - fi;                            // f in [-0.5, 0.5]
    float p = 1.54035303933e-4f;
    p = fmaf(p, f, 1.33335581464e-3f);
    p = fmaf(p, f, 9.61812910763e-3f);
    p = fmaf(p, f, 5.55041086648e-2f);
    p = fmaf(p, f, 2.40226506959e-1f);
    p = fmaf(p, f, 6.93147180560e-1f);
    p = fmaf(p, f, 1.0f);
    return p * __int_as_float((e + 127) << 23);  // * 2^e
}

// ---------------------------------------------------------------------------
// tf32 helpers (3xTF32 split for fp32-accurate tensor-core GEMM)
// ---------------------------------------------------------------------------
__device__ __forceinline__ uint32_t tf32_rna(float x) {
    uint32_t r;
    asm("cvt.rna.tf32.f32 %0, %1;" : "=r"(r) : "f"(x));
    return r;
}

__device__ __forceinline__ void mma_tf32(float* d, const uint32_t* a,
                                         const uint32_t* b) {
    asm volatile(
        "mma.sync.aligned.m16n8k8.row.col.f32.tf32.tf32.f32 "
        "{%0,%1,%2,%3}, {%4,%5,%6,%7}, {%8,%9}, {%0,%1,%2,%3};\n"
        : "+f"(d[0]), "+f"(d[1]), "+f"(d[2]), "+f"(d[3])
        : "r"(a[0]), "r"(a[1]), "r"(a[2]), "r"(a[3]),
          "r"(b[0]), "r"(b[1]));
}

// ---------------------------------------------------------------------------
// GEMM: C[M,N] = A[M,K] @ W[N,K]^T + bias   via mma.sync m16n8k8 tf32,
// 3-term split (Ah*Wh + Ah*Wl + Al*Wh) for ~fp32 accuracy at K=1024.
// 128x128 block tile, BK=16, 256 threads, 8 warps as 2(M)x4(N) of 64x32.
// Smem row stride 20 floats: frag LDS bank-perm conflict-free, STS.128 optimal.
// MODE 1: A = input, write remapped to g_Q/g_K/g_V as [B,H,S,DK]
// MODE 0: A = g_attn, write plain [M,N] to outp (final projection)
// ---------------------------------------------------------------------------
#define SKW 20   // smem stride (floats) for 16-wide K panel

template <int MODE>
__global__ __launch_bounds__(256) void gemm_k(const float* __restrict__ Ain,
                                              const float* __restrict__ W,
                                              const float* __restrict__ bias,
                                              float* __restrict__ outp,
                                              int which) {
    __shared__ __align__(16) uint32_t Ah[128 * SKW];
    __shared__ __align__(16) uint32_t Al[128 * SKW];
    __shared__ __align__(16) uint32_t Wh[128 * SKW];
    __shared__ __align__(16) uint32_t Wl[128 * SKW];

    const int tid  = threadIdx.x;
    const int lane = tid & 31;
    const int w    = tid >> 5;
    const int wm   = w >> 2;          // 0..1  (64-row slab)
    const int wn   = w & 3;           // 0..3  (32-col slab)
    const int g    = lane >> 2;       // 0..7
    const int c    = lane & 3;        // 0..3
    const int m0   = blockIdx.y << 7;
    const int n0   = blockIdx.x << 7;

    const float* A = (MODE == 0) ? g_attn : Ain;

    float acc[4][4][4];
#pragma unroll
    for (int mt = 0; mt < 4; mt++)
#pragma unroll
        for (int nt = 0; nt < 4; nt++)
#pragma unroll
            for (int r = 0; r < 4; r++) acc[mt][nt][r] = 0.f;

    const int lrow = tid >> 2;        // 0..63  (+64 on second pass)
    const int lq   = (tid & 3) << 2;  // k offset 0,4,8,12

    for (int k0 = 0; k0 < Dn; k0 += 16) {
        __syncthreads();   // previous compute done before overwrite
#pragma unroll
        for (int i = 0; i < 2; i++) {
            int row = lrow + (i << 6);
            float4 a = *(const float4*)(A + (size_t)(m0 + row) * Dn + k0 + lq);
            uint4 h4, l4;
            h4.x = tf32_rna(a.x); l4.x = tf32_rna(a.x - __uint_as_float(h4.x));
            h4.y = tf32_rna(a.y); l4.y = tf32_rna(a.y - __uint_as_float(h4.y));
            h4.z = tf32_rna(a.z); l4.z = tf32_rna(a.z - __uint_as_float(h4.z));
            h4.w = tf32_rna(a.w); l4.w = tf32_rna(a.w - __uint_as_float(h4.w));
            *(uint4*)&Ah[row * SKW + lq] = h4;
            *(uint4*)&Al[row * SKW + lq] = l4;

            float4 b = *(const float4*)(W + (size_t)(n0 + row) * Dn + k0 + lq);
            h4.x = tf32_rna(b.x); l4.x = tf32_rna(b.x - __uint_as_float(h4.x));
            h4.y = tf32_rna(b.y); l4.y = tf32_rna(b.y - __uint_as_float(h4.y));
            h4.z = tf32_rna(b.z); l4.z = tf32_rna(b.z - __uint_as_float(h4.z));
            h4.w = tf32_rna(b.w); l4.w = tf32_rna(b.w - __uint_as_float(h4.w));
            *(uint4*)&Wh[row * SKW + lq] = h4;
            *(uint4*)&Wl[row * SKW + lq] = l4;
        }
        __syncthreads();

#pragma unroll
        for (int kk = 0; kk < 16; kk += 8) {
            uint32_t a_h[4][4], a_l[4][4], b_h[4][2], b_l[4][2];
#pragma unroll
            for (int mt = 0; mt < 4; mt++) {
                int base = ((wm << 6) + (mt << 4) + g) * SKW + kk + c;
                a_h[mt][0] = Ah[base];           a_h[mt][1] = Ah[base + 8 * SKW];
                a_h[mt][2] = Ah[base + 4];       a_h[mt][3] = Ah[base + 8 * SKW + 4];
                a_l[mt][0] = Al[base];           a_l[mt][1] = Al[base + 8 * SKW];
                a_l[mt][2] = Al[base + 4];       a_l[mt][3] = Al[base + 8 * SKW + 4];
            }
#pragma unroll
            for (int nt = 0; nt < 4; nt++) {
                int base = ((wn << 5) + (nt << 3) + g) * SKW + kk + c;
                b_h[nt][0] = Wh[base];           b_h[nt][1] = Wh[base + 4];
                b_l[nt][0] = Wl[base];           b_l[nt][1] = Wl[base + 4];
            }
#pragma unroll
            for (int mt = 0; mt < 4; mt++)
#pragma unroll
                for (int nt = 0; nt < 4; nt++) {
                    mma_tf32(acc[mt][nt], a_h[mt], b_h[nt]);
                    mma_tf32(acc[mt][nt], a_h[mt], b_l[nt]);
                    mma_tf32(acc[mt][nt], a_l[mt], b_h[nt]);
                }
        }
    }

    // Epilogue: c0,c1 at (row g, cols 2c,2c+1); c2,c3 at (row g+8, same cols)
#pragma unroll
    for (int mt = 0; mt < 4; mt++) {
#pragma unroll
        for (int nt = 0; nt < 4; nt++) {
            int col = n0 + (wn << 5) + (nt << 3) + (c << 1);
            float b0 = bias[col], b1 = bias[col + 1];
#pragma unroll
            for (int half = 0; half < 2; half++) {
                int m = m0 + (wm << 6) + (mt << 4) + g + (half << 3);
                float2 v;
                v.x = acc[mt][nt][half * 2 + 0] + b0;
                v.y = acc[mt][nt][half * 2 + 1] + b1;
                if (MODE == 1) {
                    int bb = m >> 11;
                    int ss = m & (Sn - 1);
                    int h  = col >> 6;
                    int d  = col & 63;
                    float* outg = (which == 0) ? g_Q : (which == 1) ? g_K : g_V;
                    *(float2*)&outg[(((size_t)bb * Hn + h) * Sn + ss) * DKn + d] = v;
                } else {
                    *(float2*)&outp[(size_t)m * Dn + col] = v;
                }
            }
        }
    }
}

// ---------------------------------------------------------------------------
// Flash attention, fp32 SIMT (unchanged, known-good). One block = 64 query
// rows of one (b,h). 256 threads, 4x4 microtile. Rotation-skewed smem.
// ---------------------------------------------------------------------------
__global__ __launch_bounds__(256) void attn_kernel(const int* __restrict__ mask) {
    __shared__ float Qs[64 * 64];
    __shared__ float KPs[64 * 64];
    __shared__ float Vs[64 * 64];

    const int tid = threadIdx.x;
    const int tx = tid & 15;
    const int ty = tid >> 4;
    const int q0 = blockIdx.x << 6;
    const int h  = blockIdx.y;
    const int b  = blockIdx.z;

    const size_t head_off = ((size_t)b * Hn + h) * Sn * DKn;
    const float* Qg = g_Q + head_off + (size_t)q0 * DKn;
    const float* Kg = g_K + head_off;
    const float* Vg = g_V + head_off;
    const int* mrow = mask + (size_t)b * Sn * Sn + (size_t)q0 * Sn;

    const int ri0 = ty << 2;
    const int cj0 = tx << 2;
    const int rotq = (ty & 1) << 4;

#pragma unroll
    for (int i = 0; i < 4; i++) {
        int v = tid + (i << 8);
        int row = v >> 4;
        int c = (v & 15) << 2;
        float4 qv = *(const float4*)(Qg + (size_t)row * DKn + c);
        int rot = ((row >> 2) & 1) << 4;
        Qs[row * 64 + ((c + 0 + rot) & 63)] = qv.x;
        Qs[row * 64 + ((c + 1 + rot) & 63)] = qv.y;
        Qs[row * 64 + ((c + 2 + rot) & 63)] = qv.z;
        Qs[row * 64 + ((c + 3 + rot) & 63)] = qv.w;
    }

    float O[4][4];
    float mx[4], l[4];
#pragma unroll
    for (int i = 0; i < 4; i++) {
        mx[i] = -1e30f; l[i] = 0.f;
#pragma unroll
        for (int j = 0; j < 4; j++) O[i][j] = 0.f;
    }

    for (int kt = 0; kt < Sn / 64; kt++) {
        const int k0 = kt << 6;
        __syncthreads();

#pragma unroll
        for (int i = 0; i < 4; i++) {
            int v = tid + (i << 8);
            int row = v >> 4;
            int c = (v & 15) << 2;
            float4 kv = *(const float4*)(Kg + (size_t)(k0 + row) * DKn + c);
            int rot = row >> 2;
            KPs[row * 64 + ((c + 0 + rot) & 63)] = kv.x;
            KPs[row * 64 + ((c + 1 + rot) & 63)] = kv.y;
            KPs[row * 64 + ((c + 2 + rot) & 63)] = kv.z;
            KPs[row * 64 + ((c + 3 + rot) & 63)] = kv.w;
            *(float4*)&Vs[row * 64 + c] =
                *(const float4*)(Vg + (size_t)(k0 + row) * DKn + c);
        }
        __syncthreads();

        float sA[4][4];
#pragma unroll
        for (int i = 0; i < 4; i++)
#pragma unroll
            for (int j = 0; j < 4; j++) sA[i][j] = 0.f;

#pragma unroll 8
        for (int d = 0; d < 64; d++) {
            int qoff = (d + rotq) & 63;
            int koff = (d + tx) & 63;
            float qv[4], kv[4];
#pragma unroll
            for (int i = 0; i < 4; i++) qv[i] = Qs[(ri0 + i) * 64 + qoff];
#pragma unroll
            for (int j = 0; j < 4; j++) kv[j] = KPs[(cj0 + j) * 64 + koff];
#pragma unroll
            for (int i = 0; i < 4; i++)
#pragma unroll
                for (int j = 0; j < 4; j++)
                    sA[i][j] = fmaf(qv[i], kv[j], sA[i][j]);
        }

        // scale + mask (vector int4 mask loads)
#pragma unroll
        for (int i = 0; i < 4; i++) {
            const int4 mv = *(const int4*)(mrow + (size_t)(ri0 + i) * Sn + k0 + cj0);
            sA[i][0] = (mv.x == 0) ? -1e9f : sA[i][0] * 0.125f;
            sA[i][1] = (mv.y == 0) ? -1e9f : sA[i][1] * 0.125f;
            sA[i][2] = (mv.z == 0) ? -1e9f : sA[i][2] * 0.125f;
            sA[i][3] = (mv.w == 0) ? -1e9f : sA[i][3] * 0.125f;
        }

        float p[4][4];
#pragma unroll
        for (int i = 0; i < 4; i++) {
            float rm = fmaxf(fmaxf(sA[i][0], sA[i][1]), fmaxf(sA[i][2], sA[i][3]));
            rm = fmaxf(rm, __shfl_xor_sync(0xffffffffu, rm, 1));
            rm = fmaxf(rm, __shfl_xor_sync(0xffffffffu, rm, 2));
            rm = fmaxf(rm, __shfl_xor_sync(0xffffffffu, rm, 4));
            rm = fmaxf(rm, __shfl_xor_sync(0xffffffffu, rm, 8));
            float mnew = fmaxf(mx[i], rm);
            float alpha = fast_exp(mx[i] - mnew);
            mx[i] = mnew;
            float rs = 0.f;
#pragma unroll
            for (int j = 0; j < 4; j++) {
                p[i][j] = fast_exp(sA[i][j] - mnew);
                rs += p[i][j];
            }
            rs += __shfl_xor_sync(0xffffffffu, rs, 1);
            rs += __shfl_xor_sync(0xffffffffu, rs, 2);
            rs += __shfl_xor_sync(0xffffffffu, rs, 4);
            rs += __shfl_xor_sync(0xffffffffu, rs, 8);
            l[i] = l[i] * alpha + rs;
#pragma unroll
            for (int j = 0; j < 4; j++) O[i][j] *= alpha;
        }

        __syncthreads();

#pragma unroll
        for (int i = 0; i < 4; i++)
#pragma unroll
            for (int j = 0; j < 4; j++)
                KPs[(ri0 + i) * 64 + ((cj0 + j + rotq) & 63)] = p[i][j];
        __syncthreads();

#pragma unroll 8
        for (int k = 0; k < 64; k++) {
            float4 v4 = *(const float4*)&Vs[k * 64 + cj0];
            int poff = (k + rotq) & 63;
            float pv[4];
#pragma unroll
            for (int i = 0; i < 4; i++) pv[i] = KPs[(ri0 + i) * 64 + poff];
#pragma unroll
            for (int i = 0; i < 4; i++) {
                O[i][0] = fmaf(pv[i], v4.x, O[i][0]);
                O[i][1] = fmaf(pv[i], v4.y, O[i][1]);
                O[i][2] = fmaf(pv[i], v4.z, O[i][2]);
                O[i][3] = fmaf(pv[i], v4.w, O[i][3]);
            }
        }
    }

    float* og = g_attn + ((size_t)b * Sn + q0) * Dn + h * DKn;
#pragma unroll
    for (int i = 0; i < 4; i++) {
        float inv = 1.0f / l[i];
#pragma unroll
        for (int j = 0; j < 4; j++)
            og[(size_t)(ri0 + i) * Dn + cj0 + j] = O[i][j] * inv;
    }
}

// ---------------------------------------------------------------------------
// kernel_launch: 5 kernel launches on the default stream (graph-capturable)
// ---------------------------------------------------------------------------
extern "C" void kernel_launch(void* const* d_in, const int* in_sizes, int n_in,
                              void* d_out, int out_size) {
    (void)in_sizes; (void)n_in; (void)out_size;
    const float* query = (const float*)d_in[0];
    const float* key   = (const float*)d_in[1];
    const float* value = (const float*)d_in[2];
    const int*   mask  = (const int*)d_in[3];
    const float* Wq = (const float*)d_in[4];
    const float* bq = (const float*)d_in[5];
    const float* Wk = (const float*)d_in[6];
    const float* bk = (const float*)d_in[7];
    const float* Wv = (const float*)d_in[8];
    const float* bv = (const float*)d_in[9];
    const float* Wo = (const float*)d_in[10];
    const float* bo = (const float*)d_in[11];

    dim3 gg(Dn / 128, Mn / 128);   // (8, 64)
    gemm_k<1><<<gg, 256>>>(query, Wq, bq, nullptr, 0);
    gemm_k<1><<<gg, 256>>>(key,   Wk, bk, nullptr, 1);
    gemm_k<1><<<gg, 256>>>(value, Wv, bv, nullptr, 2);

    attn_kernel<<<dim3(Sn / 64, Hn, Bn), 256>>>(mask);

    gemm_k<0><<<gg, 256>>>(nullptr, Wo, bo, (float*)d_out, 0);
}